// round 5
// baseline (speedup 1.0000x reference)
#include <cuda_runtime.h>
#include <math.h>

#define NN 50000
#define NE 800000
#define NH 3

#define SCAN_B 512
#define SCAN_NB 98            // 98*512 = 50176 >= NN+1

// ---------------- scratch (device globals) ----------------
__device__ float  g_feat[NN * 192];    // projected features (stride 192 or 8)
__device__ float4 g_el4[NN];           // el per node, heads in xyz
__device__ float4 g_er4[NN];
__device__ float4 g_alpha4[NE];        // unnormalized exp per CSR pos, heads in xyz
__device__ float4 g_sinv4[NN];         // 1/sum per (dst,head)
__device__ float  g_h[NN * 64];        // inter-layer node features

__device__ int g_deg[SCAN_NB * SCAN_B];
__device__ int g_off[SCAN_NB * SCAN_B + 64];
__device__ int g_cur[NN];
__device__ int g_bsum[SCAN_NB + 8];
__device__ int g_csrc[NE];             // src node per CSR position

// ---------------- CSR build ----------------
__global__ void k_zero_deg() {
    int i = blockIdx.x * blockDim.x + threadIdx.x;
    if (i < SCAN_NB * SCAN_B) g_deg[i] = 0;
}

__global__ void k_count(const int* __restrict__ dst) {
    int e = blockIdx.x * blockDim.x + threadIdx.x;
    if (e < NE) atomicAdd(&g_deg[__ldg(dst + e)], 1);
}

__global__ void k_scan1() {
    __shared__ int s[SCAN_B];
    int t = threadIdx.x;
    int i = blockIdx.x * SCAN_B + t;
    int v = g_deg[i];
    s[t] = v;
    __syncthreads();
    for (int o = 1; o < SCAN_B; o <<= 1) {
        int x = (t >= o) ? s[t - o] : 0;
        __syncthreads();
        s[t] += x;
        __syncthreads();
    }
    g_off[i] = s[t] - v;               // exclusive within block
    if (t == SCAN_B - 1) g_bsum[blockIdx.x] = s[t];
}

__global__ void k_scan2() {             // 1 block of 128: scan 98 block sums
    __shared__ int s[128];
    int t = threadIdx.x;
    int v = (t < SCAN_NB) ? g_bsum[t] : 0;
    s[t] = v;
    __syncthreads();
    for (int o = 1; o < 128; o <<= 1) {
        int x = (t >= o) ? s[t - o] : 0;
        __syncthreads();
        s[t] += x;
        __syncthreads();
    }
    if (t < SCAN_NB) g_bsum[t] = s[t] - v;   // exclusive
}

__global__ void k_scan3() {
    int i = blockIdx.x * blockDim.x + threadIdx.x;
    if (i >= SCAN_NB * SCAN_B) return;
    int o = g_off[i] + g_bsum[i / SCAN_B];
    g_off[i] = o;
    if (i < NN) g_cur[i] = o;
}

__global__ void k_fill(const int* __restrict__ src, const int* __restrict__ dst) {
    int e = blockIdx.x * blockDim.x + threadIdx.x;
    if (e >= NE) return;
    int d = __ldg(dst + e);
    int pos = atomicAdd(&g_cur[d], 1);
    g_csrc[pos] = __ldg(src + e);
}

// ---------------- GEMMs ----------------
// layer 1: fin=9, ftot=192 (float4 over channels)
__global__ void k_gemm_l1(const float* __restrict__ x, const float* __restrict__ W) {
    int i = blockIdx.x * blockDim.x + threadIdx.x;
    if (i >= NN * 48) return;
    int n = i / 48, c4 = i - n * 48;
    const float* xr = x + n * 9;
    float4 acc = {0.f, 0.f, 0.f, 0.f};
    #pragma unroll
    for (int k = 0; k < 9; k++) {
        float xv = __ldg(xr + k);
        float4 w = __ldg((const float4*)(W + k * 192) + c4);
        acc.x = fmaf(xv, w.x, acc.x);
        acc.y = fmaf(xv, w.y, acc.y);
        acc.z = fmaf(xv, w.z, acc.z);
        acc.w = fmaf(xv, w.w, acc.w);
    }
    ((float4*)g_feat)[i] = acc;
}

// layer 2: fin=64, ftot=192, 8 channels per thread
__global__ void k_gemm_l2(const float* __restrict__ x, const float* __restrict__ W) {
    int i = blockIdx.x * blockDim.x + threadIdx.x;
    if (i >= NN * 24) return;
    int n = i / 24, c = i - n * 24;
    const float*  xr = x + n * 64;
    const float4* Wp = (const float4*)W + c * 2;
    float4 A = {0.f,0.f,0.f,0.f}, B = {0.f,0.f,0.f,0.f};
    #pragma unroll 8
    for (int k = 0; k < 64; k++) {
        float  xv = __ldg(xr + k);
        float4 w0 = __ldg(Wp + k * 48);
        float4 w1 = __ldg(Wp + k * 48 + 1);
        A.x = fmaf(xv, w0.x, A.x); A.y = fmaf(xv, w0.y, A.y);
        A.z = fmaf(xv, w0.z, A.z); A.w = fmaf(xv, w0.w, A.w);
        B.x = fmaf(xv, w1.x, B.x); B.y = fmaf(xv, w1.y, B.y);
        B.z = fmaf(xv, w1.z, B.z); B.w = fmaf(xv, w1.w, B.w);
    }
    float4* o = (float4*)g_feat + n * 48 + c * 2;
    o[0] = A; o[1] = B;
}

// layer 3: fin=64, ftot=6, output stride 8 (padded)
__global__ void k_gemm_l3(const float* __restrict__ x, const float* __restrict__ W) {
    int i = blockIdx.x * blockDim.x + threadIdx.x;
    if (i >= NN * 3) return;
    int n = i / 3, c = i - n * 3;
    const float* xr = x + n * 64;
    float a0 = 0.f, a1 = 0.f;
    #pragma unroll 8
    for (int k = 0; k < 64; k++) {
        float xv = __ldg(xr + k);
        float2 w = __ldg((const float2*)(W + k * 6) + c);
        a0 = fmaf(xv, w.x, a0);
        a1 = fmaf(xv, w.y, a1);
    }
    g_feat[n * 8 + c * 2 + 0] = a0;
    g_feat[n * 8 + c * 2 + 1] = a1;
}

// ---------------- attention logits ----------------
__global__ void k_attn(const float* __restrict__ al, const float* __restrict__ ar,
                       int fo, int st) {
    int i = blockIdx.x * blockDim.x + threadIdx.x;
    if (i >= NN * NH) return;
    int n = i / NH, h = i - n * NH;
    const float* fr = g_feat + n * st + h * fo;
    float a = 0.f, b = 0.f;
    for (int f = 0; f < fo; f++) {
        float v = fr[f];
        a = fmaf(v, __ldg(al + h * fo + f), a);
        b = fmaf(v, __ldg(ar + h * fo + f), b);
    }
    ((float*)g_el4)[n * 4 + h] = a;
    ((float*)g_er4)[n * 4 + h] = b;
}

// ---------------- edge softmax: warp per dst, all heads ----------------
__global__ void k_alpha() {
    int gw = (blockIdx.x * blockDim.x + threadIdx.x) >> 5;
    if (gw >= NN) return;
    int lane = threadIdx.x & 31;
    int b0 = g_off[gw], b1 = g_off[gw + 1];
    float4 er = g_er4[gw];
    float m0 = -INFINITY, m1 = -INFINITY, m2 = -INFINITY;
    for (int p = b0 + lane; p < b1; p += 32) {
        int s = g_csrc[p];
        float4 el = g_el4[s];
        float v0 = el.x + er.x; v0 = v0 > 0.f ? v0 : 0.2f * v0;
        float v1 = el.y + er.y; v1 = v1 > 0.f ? v1 : 0.2f * v1;
        float v2 = el.z + er.z; v2 = v2 > 0.f ? v2 : 0.2f * v2;
        g_alpha4[p] = make_float4(v0, v1, v2, 0.f);
        m0 = fmaxf(m0, v0); m1 = fmaxf(m1, v1); m2 = fmaxf(m2, v2);
    }
    #pragma unroll
    for (int o = 16; o > 0; o >>= 1) {
        m0 = fmaxf(m0, __shfl_xor_sync(0xffffffffu, m0, o));
        m1 = fmaxf(m1, __shfl_xor_sync(0xffffffffu, m1, o));
        m2 = fmaxf(m2, __shfl_xor_sync(0xffffffffu, m2, o));
    }
    float s0 = 0.f, s1 = 0.f, s2 = 0.f;
    for (int p = b0 + lane; p < b1; p += 32) {
        float4 v = g_alpha4[p];
        float e0 = __expf(v.x - m0);
        float e1 = __expf(v.y - m1);
        float e2 = __expf(v.z - m2);
        g_alpha4[p] = make_float4(e0, e1, e2, 0.f);
        s0 += e0; s1 += e1; s2 += e2;
    }
    #pragma unroll
    for (int o = 16; o > 0; o >>= 1) {
        s0 += __shfl_xor_sync(0xffffffffu, s0, o);
        s1 += __shfl_xor_sync(0xffffffffu, s1, o);
        s2 += __shfl_xor_sync(0xffffffffu, s2, o);
    }
    if (lane == 0)
        g_sinv4[gw] = make_float4(1.f / s0, 1.f / s1, 1.f / s2, 0.f);
}

// ---------------- aggregation + head-sum + bias (Fo=64) ----------------
// warp per dst; lane = float2 of the 64 output features; 3 heads in registers
__global__ void k_aggr64(const float* __restrict__ bias, float* __restrict__ out) {
    int gw = (blockIdx.x * blockDim.x + threadIdx.x) >> 5;
    if (gw >= NN) return;
    int lane = threadIdx.x & 31;
    int b0 = g_off[gw], b1 = g_off[gw + 1];
    float4 si = g_sinv4[gw];
    float2 a0 = {0.f,0.f}, a1 = {0.f,0.f}, a2 = {0.f,0.f};
    for (int p = b0; p < b1; p++) {
        int s = g_csrc[p];
        float4 ex = g_alpha4[p];
        float w0 = ex.x * si.x, w1 = ex.y * si.y, w2 = ex.z * si.z;
        const float2* f = (const float2*)g_feat + s * 96;
        float2 v0 = f[lane], v1 = f[32 + lane], v2 = f[64 + lane];
        a0.x = fmaf(w0, v0.x, a0.x); a0.y = fmaf(w0, v0.y, a0.y);
        a1.x = fmaf(w1, v1.x, a1.x); a1.y = fmaf(w1, v1.y, a1.y);
        a2.x = fmaf(w2, v2.x, a2.x); a2.y = fmaf(w2, v2.y, a2.y);
    }
    const float2* bp = (const float2*)bias;
    float2 bv0 = __ldg(bp + lane), bv1 = __ldg(bp + 32 + lane), bv2 = __ldg(bp + 64 + lane);
    float2 o;
    o.x = a0.x + a1.x + a2.x + bv0.x + bv1.x + bv2.x;
    o.y = a0.y + a1.y + a2.y + bv0.y + bv1.y + bv2.y;
    ((float2*)out)[gw * 32 + lane] = o;
}

// ---------------- aggregation + head-sum + bias (Fo=2) ----------------
__global__ void k_aggr2(const float* __restrict__ bias, float* __restrict__ out) {
    int d = blockIdx.x * blockDim.x + threadIdx.x;
    if (d >= NN) return;
    int b0 = g_off[d], b1 = g_off[d + 1];
    float4 si = g_sinv4[d];
    float o0 = 0.f, o1 = 0.f;
    for (int p = b0; p < b1; p++) {
        int s = g_csrc[p];
        float4 ex = g_alpha4[p];
        float w0 = ex.x * si.x, w1 = ex.y * si.y, w2 = ex.z * si.z;
        const float4* fp = (const float4*)(g_feat + s * 8);
        float4 f4 = fp[0];                     // h0f0,h0f1,h1f0,h1f1
        float2 f2 = *(const float2*)(g_feat + s * 8 + 4);  // h2f0,h2f1
        o0 += w0 * f4.x + w1 * f4.z + w2 * f2.x;
        o1 += w0 * f4.y + w1 * f4.w + w2 * f2.y;
    }
    float bs0 = __ldg(bias + 0) + __ldg(bias + 2) + __ldg(bias + 4);
    float bs1 = __ldg(bias + 1) + __ldg(bias + 3) + __ldg(bias + 5);
    out[d * 2 + 0] = o0 + bs0;
    out[d * 2 + 1] = o1 + bs1;
}

// ---------------- host side ----------------
static inline int cdiv(int a, int b) { return (a + b - 1) / b; }

extern "C" void kernel_launch(void* const* d_in, const int* in_sizes, int n_in,
                              void* d_out, int out_size) {
    const float* feats = (const float*)d_in[0];
    const int*   src   = (const int*)d_in[1];
    const int*   dst   = (const int*)d_in[2];
    const float* W1  = (const float*)d_in[3];
    const float* al1 = (const float*)d_in[4];
    const float* ar1 = (const float*)d_in[5];
    const float* b1  = (const float*)d_in[6];
    const float* W2  = (const float*)d_in[7];
    const float* al2 = (const float*)d_in[8];
    const float* ar2 = (const float*)d_in[9];
    const float* b2  = (const float*)d_in[10];
    const float* W3  = (const float*)d_in[11];
    const float* al3 = (const float*)d_in[12];
    const float* ar3 = (const float*)d_in[13];
    const float* b3  = (const float*)d_in[14];

    const int B = 256;

    // Build CSR once (reused by all 3 layers)
    k_zero_deg<<<cdiv(SCAN_NB * SCAN_B, B), B>>>();
    k_count<<<cdiv(NE, B), B>>>(dst);
    k_scan1<<<SCAN_NB, SCAN_B>>>();
    k_scan2<<<1, 128>>>();
    k_scan3<<<cdiv(SCAN_NB * SCAN_B, B), B>>>();
    k_fill<<<cdiv(NE, B), B>>>(src, dst);

    float* hbuf = nullptr;
    cudaGetSymbolAddress((void**)&hbuf, g_h);

    // layer 1
    k_gemm_l1<<<cdiv(NN * 48, B), B>>>(feats, W1);
    k_attn<<<cdiv(NN * NH, B), B>>>(al1, ar1, 64, 192);
    k_alpha<<<cdiv(NN * 32, B), B>>>();
    k_aggr64<<<cdiv(NN * 32, B), B>>>(b1, hbuf);

    // layer 2
    k_gemm_l2<<<cdiv(NN * 24, B), B>>>(hbuf, W2);
    k_attn<<<cdiv(NN * NH, B), B>>>(al2, ar2, 64, 192);
    k_alpha<<<cdiv(NN * 32, B), B>>>();
    k_aggr64<<<cdiv(NN * 32, B), B>>>(b2, hbuf);

    // layer 3
    k_gemm_l3<<<cdiv(NN * 3, B), B>>>(hbuf, W3);
    k_attn<<<cdiv(NN * NH, B), B>>>(al3, ar3, 2, 8);
    k_alpha<<<cdiv(NN * 32, B), B>>>();
    k_aggr2<<<cdiv(NN, B), B>>>(b3, (float*)d_out);
}

// round 9
// speedup vs baseline: 1.4342x; 1.4342x over previous
#include <cuda_runtime.h>
#include <math.h>

#define NN 50000
#define NE 800000
#define NH 3
#define FMAX 192

#define SCAN_B 512
#define SCAN_NB 98            // 98*512 = 50176 >= NN+1

// ---------------- scratch (device globals) ----------------
__device__ float g_feat[NN * FMAX];    // projected features [N, H*Fo]
__device__ float g_el[NN * NH];
__device__ float g_er[NN * NH];
__device__ float g_alpha[NE * NH];     // unnormalized exp per (csr_pos, head)
__device__ float g_sinv[NN * NH];      // 1/sum per (dst, head)
__device__ float g_rst[NN * FMAX];     // aggregation output
__device__ float g_h[NN * 64];         // inter-layer node features

__device__ int g_deg[SCAN_NB * SCAN_B];
__device__ int g_off[SCAN_NB * SCAN_B + 64];
__device__ int g_cur[NN];
__device__ int g_bsum[SCAN_NB + 8];
__device__ int g_csrc[NE];             // src node per CSR position

// ---------------- CSR build ----------------
__global__ void k_zero_deg() {
    int i = blockIdx.x * blockDim.x + threadIdx.x;
    if (i < SCAN_NB * SCAN_B) g_deg[i] = 0;
}

__global__ void k_count(const int* __restrict__ dst) {
    int e = blockIdx.x * blockDim.x + threadIdx.x;
    if (e < NE) atomicAdd(&g_deg[__ldg(dst + e)], 1);
}

__global__ void k_scan1() {
    __shared__ int s[SCAN_B];
    int t = threadIdx.x;
    int i = blockIdx.x * SCAN_B + t;
    int v = g_deg[i];
    s[t] = v;
    __syncthreads();
    for (int o = 1; o < SCAN_B; o <<= 1) {
        int x = (t >= o) ? s[t - o] : 0;
        __syncthreads();
        s[t] += x;
        __syncthreads();
    }
    g_off[i] = s[t] - v;               // exclusive within block
    if (t == SCAN_B - 1) g_bsum[blockIdx.x] = s[t];
}

__global__ void k_scan2() {             // 1 block of 128: scan 98 block sums
    __shared__ int s[128];
    int t = threadIdx.x;
    int v = (t < SCAN_NB) ? g_bsum[t] : 0;
    s[t] = v;
    __syncthreads();
    for (int o = 1; o < 128; o <<= 1) {
        int x = (t >= o) ? s[t - o] : 0;
        __syncthreads();
        s[t] += x;
        __syncthreads();
    }
    if (t < SCAN_NB) g_bsum[t] = s[t] - v;   // exclusive
}

__global__ void k_scan3() {
    int i = blockIdx.x * blockDim.x + threadIdx.x;
    if (i >= SCAN_NB * SCAN_B) return;
    int o = g_off[i] + g_bsum[i / SCAN_B];
    g_off[i] = o;
    if (i < NN) g_cur[i] = o;
}

__global__ void k_fill(const int* __restrict__ src, const int* __restrict__ dst) {
    int e = blockIdx.x * blockDim.x + threadIdx.x;
    if (e >= NE) return;
    int d = __ldg(dst + e);
    int pos = atomicAdd(&g_cur[d], 1);
    g_csrc[pos] = __ldg(src + e);
}

// ---------------- per-layer kernels ----------------
// scalar GEMM (used when ftot % 4 != 0)
__global__ void k_gemm(const float* __restrict__ x, const float* __restrict__ W,
                       int fin, int ftot) {
    int i = blockIdx.x * blockDim.x + threadIdx.x;
    if (i >= NN * ftot) return;
    int n = i / ftot, c = i - n * ftot;
    const float* xr = x + n * fin;
    float acc = 0.f;
    #pragma unroll 4
    for (int k = 0; k < fin; k++) acc = fmaf(__ldg(xr + k), __ldg(W + k * ftot + c), acc);
    g_feat[i] = acc;
}

// float4 GEMM over output channels
__global__ void k_gemm_v4(const float* __restrict__ x, const float* __restrict__ W,
                          int fin, int ftot) {
    int nvec = ftot >> 2;
    int i = blockIdx.x * blockDim.x + threadIdx.x;
    if (i >= NN * nvec) return;
    int n = i / nvec, c4 = i - n * nvec;
    const float* xr = x + n * fin;
    float4 acc = {0.f, 0.f, 0.f, 0.f};
    #pragma unroll 4
    for (int k = 0; k < fin; k++) {
        float xv = __ldg(xr + k);
        float4 w = __ldg((const float4*)(W + k * ftot + c4 * 4));
        acc.x = fmaf(xv, w.x, acc.x);
        acc.y = fmaf(xv, w.y, acc.y);
        acc.z = fmaf(xv, w.z, acc.z);
        acc.w = fmaf(xv, w.w, acc.w);
    }
    ((float4*)g_feat)[i] = acc;
}

__global__ void k_attn(const float* __restrict__ al, const float* __restrict__ ar, int fo) {
    int i = blockIdx.x * blockDim.x + threadIdx.x;
    if (i >= NN * NH) return;
    int n = i / NH, h = i - n * NH;
    const float* fr = g_feat + n * NH * fo + h * fo;
    float a = 0.f, b = 0.f;
    for (int f = 0; f < fo; f++) {
        float v = fr[f];
        a = fmaf(v, __ldg(al + h * fo + f), a);
        b = fmaf(v, __ldg(ar + h * fo + f), b);
    }
    g_el[i] = a;
    g_er[i] = b;
}

// thread per (dst, head): edge softmax; store UNNORMALIZED exp + 1/sum
__global__ void k_alpha() {
    int i = blockIdx.x * blockDim.x + threadIdx.x;
    if (i >= NN * NH) return;
    int d = i / NH, h = i - d * NH;
    int b0 = g_off[d], b1 = g_off[d + 1];
    if (b0 == b1) return;
    float erd = g_er[d * NH + h];
    float m = -INFINITY;
    for (int p = b0; p < b1; p++) {
        int s = g_csrc[p];
        float v = g_el[s * NH + h] + erd;
        v = v > 0.f ? v : 0.2f * v;
        g_alpha[p * NH + h] = v;
        m = fmaxf(m, v);
    }
    float sum = 0.f;
    for (int p = b0; p < b1; p++) {
        float ex = __expf(g_alpha[p * NH + h] - m);
        g_alpha[p * NH + h] = ex;
        sum += ex;
    }
    g_sinv[i] = 1.f / sum;
}

// warp per (dst, head), lane = float2 of features (Fo=64); pipelined gather
__global__ void k_aggr64_csr() {
    int gw = (blockIdx.x * blockDim.x + threadIdx.x) >> 5;
    if (gw >= NN * NH) return;
    int lane = threadIdx.x & 31;
    int d = gw / NH, h = gw - d * NH;
    int b0 = g_off[d], b1 = g_off[d + 1];
    float2 acc = {0.f, 0.f};
    const float2* featp = (const float2*)g_feat;
    int fvec = h * 32 + lane;          // float2 index within a node's 192 floats
    if (b0 < b1) {
        float si = g_sinv[d * NH + h];
        int   s = g_csrc[b0];
        float a = g_alpha[b0 * NH + h];
        for (int p = b0; p < b1; p++) {
            int   sn = 0;
            float an = 0.f;
            if (p + 1 < b1) {                    // prefetch next edge's index+weight
                sn = g_csrc[p + 1];
                an = g_alpha[(p + 1) * NH + h];
            }
            float  w = a * si;
            float2 v = featp[s * 96 + fvec];
            acc.x = fmaf(w, v.x, acc.x);
            acc.y = fmaf(w, v.y, acc.y);
            s = sn;
            a = an;
        }
    }
    ((float2*)g_rst)[d * 96 + fvec] = acc;
}

// thread per (dst, head) for Fo=2
__global__ void k_aggr2_csr() {
    int i = blockIdx.x * blockDim.x + threadIdx.x;
    if (i >= NN * NH) return;
    int d = i / NH, h = i - d * NH;
    int b0 = g_off[d], b1 = g_off[d + 1];
    float a0 = 0.f, a1 = 0.f;
    if (b0 < b1) {
        float si = g_sinv[i];
        for (int p = b0; p < b1; p++) {
            int s = g_csrc[p];
            float a = g_alpha[p * NH + h] * si;
            a0 = fmaf(a, g_feat[s * 6 + h * 2 + 0], a0);
            a1 = fmaf(a, g_feat[s * 6 + h * 2 + 1], a1);
        }
    }
    g_rst[d * 6 + h * 2 + 0] = a0;
    g_rst[d * 6 + h * 2 + 1] = a1;
}

// out[n,f] = sum_h (rst[n,h,f] + bias[h,f])
__global__ void k_final(const float* __restrict__ bias, float* __restrict__ out, int fo) {
    int i = blockIdx.x * blockDim.x + threadIdx.x;
    if (i >= NN * fo) return;
    int n = i / fo, f = i - n * fo;
    float acc = 0.f;
    #pragma unroll
    for (int h = 0; h < NH; h++)
        acc += g_rst[n * NH * fo + h * fo + f] + __ldg(bias + h * fo + f);
    out[i] = acc;
}

// ---------------- host side ----------------
static inline int cdiv(int a, int b) { return (a + b - 1) / b; }

static void run_layer(const float* x, const float* W, const float* al,
                      const float* ar, const float* bias,
                      int fin, int fo, float* out) {
    const int B = 256;
    int ftot = NH * fo;
    if ((ftot & 3) == 0)
        k_gemm_v4<<<cdiv(NN * (ftot >> 2), B), B>>>(x, W, fin, ftot);
    else
        k_gemm<<<cdiv(NN * ftot, B), B>>>(x, W, fin, ftot);
    k_attn<<<cdiv(NN * NH, B), B>>>(al, ar, fo);
    k_alpha<<<cdiv(NN * NH, B), B>>>();
    if (fo == 64)
        k_aggr64_csr<<<cdiv(NN * NH * 32, B), B>>>();
    else
        k_aggr2_csr<<<cdiv(NN * NH, B), B>>>();
    k_final<<<cdiv(NN * fo, B), B>>>(bias, out, fo);
}

extern "C" void kernel_launch(void* const* d_in, const int* in_sizes, int n_in,
                              void* d_out, int out_size) {
    const float* feats = (const float*)d_in[0];
    const int*   src   = (const int*)d_in[1];
    const int*   dst   = (const int*)d_in[2];
    const float* W1  = (const float*)d_in[3];
    const float* al1 = (const float*)d_in[4];
    const float* ar1 = (const float*)d_in[5];
    const float* b1  = (const float*)d_in[6];
    const float* W2  = (const float*)d_in[7];
    const float* al2 = (const float*)d_in[8];
    const float* ar2 = (const float*)d_in[9];
    const float* b2  = (const float*)d_in[10];
    const float* W3  = (const float*)d_in[11];
    const float* al3 = (const float*)d_in[12];
    const float* ar3 = (const float*)d_in[13];
    const float* b3  = (const float*)d_in[14];

    const int B = 256;

    // Build CSR once (reused by all 3 layers)
    k_zero_deg<<<cdiv(SCAN_NB * SCAN_B, B), B>>>();
    k_count<<<cdiv(NE, B), B>>>(dst);
    k_scan1<<<SCAN_NB, SCAN_B>>>();
    k_scan2<<<1, 128>>>();
    k_scan3<<<cdiv(SCAN_NB * SCAN_B, B), B>>>();
    k_fill<<<cdiv(NE, B), B>>>(src, dst);

    float* hbuf = nullptr;
    cudaGetSymbolAddress((void**)&hbuf, g_h);

    run_layer(feats, W1, al1, ar1, b1, 9,  64, hbuf);
    run_layer(hbuf,  W2, al2, ar2, b2, 64, 64, hbuf);
    run_layer(hbuf,  W3, al3, ar3, b3, 64, 2,  (float*)d_out);
}

// round 10
// speedup vs baseline: 1.5757x; 1.0986x over previous
#include <cuda_runtime.h>
#include <math.h>

#define NN 50000
#define NE 800000
#define NH 3
#define FMAX 192

#define SCAN_B 512
#define SCAN_NB 98            // 98*512 = 50176 >= NN+1

// ---------------- scratch (device globals) ----------------
__device__ float g_feat[NN * FMAX];    // projected features [N, H*Fo]
__device__ float g_el[NN * NH];
__device__ float g_er[NN * NH];
__device__ float g_alpha[NE * NH];     // unnormalized exp per (csr_pos, head)
__device__ float g_sinv[NN * NH];      // 1/sum per (dst, head)
__device__ float g_rst[NN * FMAX];     // aggregation output
__device__ float g_h[NN * 64];         // inter-layer node features

__device__ int g_deg[SCAN_NB * SCAN_B];
__device__ int g_off[SCAN_NB * SCAN_B + 64];
__device__ int g_cur[NN];
__device__ int g_bsum[SCAN_NB + 8];
__device__ int g_csrc[NE];             // src node per CSR position

// ---------------- CSR build ----------------
__global__ void k_zero_deg() {
    int i = blockIdx.x * blockDim.x + threadIdx.x;
    if (i < SCAN_NB * SCAN_B) g_deg[i] = 0;
}

__global__ void k_count(const int* __restrict__ dst) {
    int e = blockIdx.x * blockDim.x + threadIdx.x;
    if (e < NE) atomicAdd(&g_deg[__ldg(dst + e)], 1);
}

__global__ void k_scan1() {
    __shared__ int s[SCAN_B];
    int t = threadIdx.x;
    int i = blockIdx.x * SCAN_B + t;
    int v = g_deg[i];
    s[t] = v;
    __syncthreads();
    for (int o = 1; o < SCAN_B; o <<= 1) {
        int x = (t >= o) ? s[t - o] : 0;
        __syncthreads();
        s[t] += x;
        __syncthreads();
    }
    g_off[i] = s[t] - v;               // exclusive within block
    if (t == SCAN_B - 1) g_bsum[blockIdx.x] = s[t];
}

__global__ void k_scan2() {             // 1 block of 128: scan 98 block sums
    __shared__ int s[128];
    int t = threadIdx.x;
    int v = (t < SCAN_NB) ? g_bsum[t] : 0;
    s[t] = v;
    __syncthreads();
    for (int o = 1; o < 128; o <<= 1) {
        int x = (t >= o) ? s[t - o] : 0;
        __syncthreads();
        s[t] += x;
        __syncthreads();
    }
    if (t < SCAN_NB) g_bsum[t] = s[t] - v;   // exclusive
}

__global__ void k_scan3() {
    int i = blockIdx.x * blockDim.x + threadIdx.x;
    if (i >= SCAN_NB * SCAN_B) return;
    int o = g_off[i] + g_bsum[i / SCAN_B];
    g_off[i] = o;
    if (i < NN) g_cur[i] = o;
}

__global__ void k_fill(const int* __restrict__ src, const int* __restrict__ dst) {
    int e = blockIdx.x * blockDim.x + threadIdx.x;
    if (e >= NE) return;
    int d = __ldg(dst + e);
    int pos = atomicAdd(&g_cur[d], 1);
    g_csrc[pos] = __ldg(src + e);
}

// ---------------- per-layer kernels ----------------
// scalar GEMM (used when ftot % 4 != 0)
__global__ void k_gemm(const float* __restrict__ x, const float* __restrict__ W,
                       int fin, int ftot) {
    int i = blockIdx.x * blockDim.x + threadIdx.x;
    if (i >= NN * ftot) return;
    int n = i / ftot, c = i - n * ftot;
    const float* xr = x + n * fin;
    float acc = 0.f;
    #pragma unroll 4
    for (int k = 0; k < fin; k++) acc = fmaf(__ldg(xr + k), __ldg(W + k * ftot + c), acc);
    g_feat[i] = acc;
}

// float4 GEMM over output channels
__global__ void k_gemm_v4(const float* __restrict__ x, const float* __restrict__ W,
                          int fin, int ftot) {
    int nvec = ftot >> 2;
    int i = blockIdx.x * blockDim.x + threadIdx.x;
    if (i >= NN * nvec) return;
    int n = i / nvec, c4 = i - n * nvec;
    const float* xr = x + n * fin;
    float4 acc = {0.f, 0.f, 0.f, 0.f};
    #pragma unroll 4
    for (int k = 0; k < fin; k++) {
        float xv = __ldg(xr + k);
        float4 w = __ldg((const float4*)(W + k * ftot + c4 * 4));
        acc.x = fmaf(xv, w.x, acc.x);
        acc.y = fmaf(xv, w.y, acc.y);
        acc.z = fmaf(xv, w.z, acc.z);
        acc.w = fmaf(xv, w.w, acc.w);
    }
    ((float4*)g_feat)[i] = acc;
}

__global__ void k_attn(const float* __restrict__ al, const float* __restrict__ ar, int fo) {
    int i = blockIdx.x * blockDim.x + threadIdx.x;
    if (i >= NN * NH) return;
    int n = i / NH, h = i - n * NH;
    const float* fr = g_feat + n * NH * fo + h * fo;
    float a = 0.f, b = 0.f;
    for (int f = 0; f < fo; f++) {
        float v = fr[f];
        a = fmaf(v, __ldg(al + h * fo + f), a);
        b = fmaf(v, __ldg(ar + h * fo + f), b);
    }
    g_el[i] = a;
    g_er[i] = b;
}

// thread per (dst, head): edge softmax; store UNNORMALIZED exp + 1/sum
__global__ void k_alpha() {
    int i = blockIdx.x * blockDim.x + threadIdx.x;
    if (i >= NN * NH) return;
    int d = i / NH, h = i - d * NH;
    int b0 = g_off[d], b1 = g_off[d + 1];
    if (b0 == b1) return;
    float erd = g_er[d * NH + h];
    float m = -INFINITY;
    for (int p = b0; p < b1; p++) {
        int s = g_csrc[p];
        float v = g_el[s * NH + h] + erd;
        v = v > 0.f ? v : 0.2f * v;
        g_alpha[p * NH + h] = v;
        m = fmaxf(m, v);
    }
    float sum = 0.f;
    for (int p = b0; p < b1; p++) {
        float ex = __expf(g_alpha[p * NH + h] - m);
        g_alpha[p * NH + h] = ex;
        sum += ex;
    }
    g_sinv[i] = 1.f / sum;
}

// warp per (dst, head), lane = float2 of features (Fo=64)
// unroll-by-2: two independent gathers in flight, no branches in body
__global__ void k_aggr64_csr() {
    int gw = (blockIdx.x * blockDim.x + threadIdx.x) >> 5;
    if (gw >= NN * NH) return;
    int lane = threadIdx.x & 31;
    int d = gw / NH, h = gw - d * NH;
    int b0 = g_off[d], b1 = g_off[d + 1];
    float2 acc0 = {0.f, 0.f}, acc1 = {0.f, 0.f};
    const float2* featp = (const float2*)g_feat;
    int fvec = h * 32 + lane;          // float2 index within a node's 192 floats
    float si = g_sinv[d * NH + h];
    int p = b0;
    for (; p + 2 <= b1; p += 2) {
        int s0 = g_csrc[p];
        int s1 = g_csrc[p + 1];
        float a0 = g_alpha[p * NH + h];
        float a1 = g_alpha[(p + 1) * NH + h];
        float2 v0 = featp[s0 * 96 + fvec];
        float2 v1 = featp[s1 * 96 + fvec];
        acc0.x = fmaf(a0, v0.x, acc0.x);
        acc0.y = fmaf(a0, v0.y, acc0.y);
        acc1.x = fmaf(a1, v1.x, acc1.x);
        acc1.y = fmaf(a1, v1.y, acc1.y);
    }
    if (p < b1) {
        int s = g_csrc[p];
        float a = g_alpha[p * NH + h];
        float2 v = featp[s * 96 + fvec];
        acc0.x = fmaf(a, v.x, acc0.x);
        acc0.y = fmaf(a, v.y, acc0.y);
    }
    float2 o;
    o.x = (acc0.x + acc1.x) * si;
    o.y = (acc0.y + acc1.y) * si;
    ((float2*)g_rst)[d * 96 + fvec] = o;
}

// thread per (dst, head) for Fo=2
__global__ void k_aggr2_csr() {
    int i = blockIdx.x * blockDim.x + threadIdx.x;
    if (i >= NN * NH) return;
    int d = i / NH, h = i - d * NH;
    int b0 = g_off[d], b1 = g_off[d + 1];
    float a0 = 0.f, a1 = 0.f;
    float si = (b0 < b1) ? g_sinv[i] : 0.f;
    for (int p = b0; p < b1; p++) {
        int s = g_csrc[p];
        float a = g_alpha[p * NH + h];
        a0 = fmaf(a, g_feat[s * 6 + h * 2 + 0], a0);
        a1 = fmaf(a, g_feat[s * 6 + h * 2 + 1], a1);
    }
    g_rst[d * 6 + h * 2 + 0] = a0 * si;
    g_rst[d * 6 + h * 2 + 1] = a1 * si;
}

// out[n,f] = sum_h (rst[n,h,f] + bias[h,f])
__global__ void k_final(const float* __restrict__ bias, float* __restrict__ out, int fo) {
    int i = blockIdx.x * blockDim.x + threadIdx.x;
    if (i >= NN * fo) return;
    int n = i / fo, f = i - n * fo;
    float acc = 0.f;
    #pragma unroll
    for (int h = 0; h < NH; h++)
        acc += g_rst[n * NH * fo + h * fo + f] + __ldg(bias + h * fo + f);
    out[i] = acc;
}

// ---------------- host side ----------------
static inline int cdiv(int a, int b) { return (a + b - 1) / b; }

static void run_layer(const float* x, const float* W, const float* al,
                      const float* ar, const float* bias,
                      int fin, int fo, float* out) {
    const int B = 256;
    int ftot = NH * fo;
    if ((ftot & 3) == 0)
        k_gemm_v4<<<cdiv(NN * (ftot >> 2), B), B>>>(x, W, fin, ftot);
    else
        k_gemm<<<cdiv(NN * ftot, B), B>>>(x, W, fin, ftot);
    k_attn<<<cdiv(NN * NH, B), B>>>(al, ar, fo);
    k_alpha<<<cdiv(NN * NH, B), B>>>();
    if (fo == 64)
        k_aggr64_csr<<<cdiv(NN * NH * 32, B), B>>>();
    else
        k_aggr2_csr<<<cdiv(NN * NH, B), B>>>();
    k_final<<<cdiv(NN * fo, B), B>>>(bias, out, fo);
}

extern "C" void kernel_launch(void* const* d_in, const int* in_sizes, int n_in,
                              void* d_out, int out_size) {
    const float* feats = (const float*)d_in[0];
    const int*   src   = (const int*)d_in[1];
    const int*   dst   = (const int*)d_in[2];
    const float* W1  = (const float*)d_in[3];
    const float* al1 = (const float*)d_in[4];
    const float* ar1 = (const float*)d_in[5];
    const float* b1  = (const float*)d_in[6];
    const float* W2  = (const float*)d_in[7];
    const float* al2 = (const float*)d_in[8];
    const float* ar2 = (const float*)d_in[9];
    const float* b2  = (const float*)d_in[10];
    const float* W3  = (const float*)d_in[11];
    const float* al3 = (const float*)d_in[12];
    const float* ar3 = (const float*)d_in[13];
    const float* b3  = (const float*)d_in[14];

    const int B = 256;

    // Build CSR once (reused by all 3 layers)
    k_zero_deg<<<cdiv(SCAN_NB * SCAN_B, B), B>>>();
    k_count<<<cdiv(NE, B), B>>>(dst);
    k_scan1<<<SCAN_NB, SCAN_B>>>();
    k_scan2<<<1, 128>>>();
    k_scan3<<<cdiv(SCAN_NB * SCAN_B, B), B>>>();
    k_fill<<<cdiv(NE, B), B>>>(src, dst);

    float* hbuf = nullptr;
    cudaGetSymbolAddress((void**)&hbuf, g_h);

    run_layer(feats, W1, al1, ar1, b1, 9,  64, hbuf);
    run_layer(hbuf,  W2, al2, ar2, b2, 64, 64, hbuf);
    run_layer(hbuf,  W3, al3, ar3, b3, 64, 2,  (float*)d_out);
}

// round 15
// speedup vs baseline: 1.5858x; 1.0064x over previous
#include <cuda_runtime.h>
#include <math.h>

#define NN 50000
#define NE 800000
#define NH 3
#define FMAX 192

#define SCAN_B 512
#define SCAN_NB 98            // 98*512 = 50176 >= NN+1

// ---------------- scratch (device globals) ----------------
__device__ float g_feat[NN * FMAX];    // projected features [N, H*Fo]
__device__ float g_el[NN * NH];
__device__ float g_er[NN * NH];
__device__ float g_alpha[NE * NH];     // unnormalized exp per (csr_pos, head)
__device__ float g_sinv[NN * NH];      // 1/sum per (dst, head)
__device__ float g_rst[NN * FMAX];     // aggregation output
__device__ float g_h[NN * 64];         // inter-layer node features

__device__ int g_deg[SCAN_NB * SCAN_B];
__device__ int g_off[SCAN_NB * SCAN_B + 64];
__device__ int g_cur[NN];
__device__ int g_bsum[SCAN_NB + 8];
__device__ int g_csrc[NE];             // src node per CSR position

// ---------------- CSR build ----------------
__global__ void k_zero_deg() {
    int i = blockIdx.x * blockDim.x + threadIdx.x;
    if (i < SCAN_NB * SCAN_B) g_deg[i] = 0;
}

__global__ void k_count(const int* __restrict__ dst) {
    int e = blockIdx.x * blockDim.x + threadIdx.x;
    if (e < NE) atomicAdd(&g_deg[__ldg(dst + e)], 1);
}

__global__ void k_scan1() {
    __shared__ int s[SCAN_B];
    int t = threadIdx.x;
    int i = blockIdx.x * SCAN_B + t;
    int v = g_deg[i];
    s[t] = v;
    __syncthreads();
    for (int o = 1; o < SCAN_B; o <<= 1) {
        int x = (t >= o) ? s[t - o] : 0;
        __syncthreads();
        s[t] += x;
        __syncthreads();
    }
    g_off[i] = s[t] - v;               // exclusive within block
    if (t == SCAN_B - 1) g_bsum[blockIdx.x] = s[t];
}

__global__ void k_scan2() {             // 1 block of 128: scan 98 block sums
    __shared__ int s[128];
    int t = threadIdx.x;
    int v = (t < SCAN_NB) ? g_bsum[t] : 0;
    s[t] = v;
    __syncthreads();
    for (int o = 1; o < 128; o <<= 1) {
        int x = (t >= o) ? s[t - o] : 0;
        __syncthreads();
        s[t] += x;
        __syncthreads();
    }
    if (t < SCAN_NB) g_bsum[t] = s[t] - v;   // exclusive
}

__global__ void k_scan3() {
    int i = blockIdx.x * blockDim.x + threadIdx.x;
    if (i >= SCAN_NB * SCAN_B) return;
    int o = g_off[i] + g_bsum[i / SCAN_B];
    g_off[i] = o;
    if (i < NN) g_cur[i] = o;
}

__global__ void k_fill(const int* __restrict__ src, const int* __restrict__ dst) {
    int e = blockIdx.x * blockDim.x + threadIdx.x;
    if (e >= NE) return;
    int d = __ldg(dst + e);
    int pos = atomicAdd(&g_cur[d], 1);
    g_csrc[pos] = __ldg(src + e);
}

// ---------------- per-layer kernels ----------------
// scalar GEMM (ftot not multiple of 4; layer 3)
__global__ void k_gemm(const float* __restrict__ x, const float* __restrict__ W,
                       int fin, int ftot) {
    int i = blockIdx.x * blockDim.x + threadIdx.x;
    if (i >= NN * ftot) return;
    int n = i / ftot, c = i - n * ftot;
    const float* xr = x + n * fin;
    float acc = 0.f;
    #pragma unroll 4
    for (int k = 0; k < fin; k++) acc = fmaf(__ldg(xr + k), __ldg(W + k * ftot + c), acc);
    g_feat[i] = acc;
}

// float4 GEMM over output channels, scalar x loads (layer 1, fin=9)
__global__ void k_gemm_v4(const float* __restrict__ x, const float* __restrict__ W,
                          int fin, int ftot) {
    int nvec = ftot >> 2;
    int i = blockIdx.x * blockDim.x + threadIdx.x;
    if (i >= NN * nvec) return;
    int n = i / nvec, c4 = i - n * nvec;
    const float* xr = x + n * fin;
    float4 acc = {0.f, 0.f, 0.f, 0.f};
    #pragma unroll 4
    for (int k = 0; k < fin; k++) {
        float xv = __ldg(xr + k);
        float4 w = __ldg((const float4*)(W + k * ftot + c4 * 4));
        acc.x = fmaf(xv, w.x, acc.x);
        acc.y = fmaf(xv, w.y, acc.y);
        acc.z = fmaf(xv, w.z, acc.z);
        acc.w = fmaf(xv, w.w, acc.w);
    }
    ((float4*)g_feat)[i] = acc;
}

// float4 GEMM, float4 x loads too (fin%4==0 && ftot%4==0; layer 2)
__global__ void k_gemm_v4x4(const float* __restrict__ x, const float* __restrict__ W,
                            int fin, int ftot) {
    int nvec = ftot >> 2;
    int i = blockIdx.x * blockDim.x + threadIdx.x;
    if (i >= NN * nvec) return;
    int n = i / nvec, c4 = i - n * nvec;
    const float4* x4 = (const float4*)(x + n * fin);
    float4 acc = {0.f, 0.f, 0.f, 0.f};
    int k4n = fin >> 2;
    #pragma unroll 2
    for (int k4 = 0; k4 < k4n; k4++) {
        float4 xv = __ldg(x4 + k4);
        const float* Wb = W + (k4 << 2) * ftot + c4 * 4;
        float4 w0 = __ldg((const float4*)(Wb));
        float4 w1 = __ldg((const float4*)(Wb + ftot));
        float4 w2 = __ldg((const float4*)(Wb + 2 * ftot));
        float4 w3 = __ldg((const float4*)(Wb + 3 * ftot));
        acc.x = fmaf(xv.x, w0.x, acc.x); acc.y = fmaf(xv.x, w0.y, acc.y);
        acc.z = fmaf(xv.x, w0.z, acc.z); acc.w = fmaf(xv.x, w0.w, acc.w);
        acc.x = fmaf(xv.y, w1.x, acc.x); acc.y = fmaf(xv.y, w1.y, acc.y);
        acc.z = fmaf(xv.y, w1.z, acc.z); acc.w = fmaf(xv.y, w1.w, acc.w);
        acc.x = fmaf(xv.z, w2.x, acc.x); acc.y = fmaf(xv.z, w2.y, acc.y);
        acc.z = fmaf(xv.z, w2.z, acc.z); acc.w = fmaf(xv.z, w2.w, acc.w);
        acc.x = fmaf(xv.w, w3.x, acc.x); acc.y = fmaf(xv.w, w3.y, acc.y);
        acc.z = fmaf(xv.w, w3.z, acc.z); acc.w = fmaf(xv.w, w3.w, acc.w);
    }
    ((float4*)g_feat)[i] = acc;
}

__global__ void k_attn(const float* __restrict__ al, const float* __restrict__ ar, int fo) {
    int i = blockIdx.x * blockDim.x + threadIdx.x;
    if (i >= NN * NH) return;
    int n = i / NH, h = i - n * NH;
    const float* fr = g_feat + n * NH * fo + h * fo;
    float a = 0.f, b = 0.f;
    for (int f = 0; f < fo; f++) {
        float v = fr[f];
        a = fmaf(v, __ldg(al + h * fo + f), a);
        b = fmaf(v, __ldg(ar + h * fo + f), b);
    }
    g_el[i] = a;
    g_er[i] = b;
}

// thread per (dst, head): edge softmax; store UNNORMALIZED exp + 1/sum
__global__ void k_alpha() {
    int i = blockIdx.x * blockDim.x + threadIdx.x;
    if (i >= NN * NH) return;
    int d = i / NH, h = i - d * NH;
    int b0 = g_off[d], b1 = g_off[d + 1];
    if (b0 == b1) return;
    float erd = g_er[d * NH + h];
    float m = -INFINITY;
    for (int p = b0; p < b1; p++) {
        int s = g_csrc[p];
        float v = g_el[s * NH + h] + erd;
        v = v > 0.f ? v : 0.2f * v;
        g_alpha[p * NH + h] = v;
        m = fmaxf(m, v);
    }
    float sum = 0.f;
    for (int p = b0; p < b1; p++) {
        float ex = __expf(g_alpha[p * NH + h] - m);
        g_alpha[p * NH + h] = ex;
        sum += ex;
    }
    g_sinv[i] = 1.f / sum;
}

// warp per (dst, head), lane = float2 of features (Fo=64)
// unroll-by-4: four independent gathers in flight, branch-free body
__global__ void k_aggr64_csr() {
    int gw = (blockIdx.x * blockDim.x + threadIdx.x) >> 5;
    if (gw >= NN * NH) return;
    int lane = threadIdx.x & 31;
    int d = gw / NH, h = gw - d * NH;
    int b0 = g_off[d], b1 = g_off[d + 1];
    float2 acc0 = {0.f, 0.f}, acc1 = {0.f, 0.f};
    float2 acc2 = {0.f, 0.f}, acc3 = {0.f, 0.f};
    const float2* featp = (const float2*)g_feat;
    int fvec = h * 32 + lane;          // float2 index within a node's 192 floats
    float si = g_sinv[d * NH + h];
    int p = b0;
    for (; p + 4 <= b1; p += 4) {
        int s0 = g_csrc[p];
        int s1 = g_csrc[p + 1];
        int s2 = g_csrc[p + 2];
        int s3 = g_csrc[p + 3];
        float a0 = g_alpha[p * NH + h];
        float a1 = g_alpha[(p + 1) * NH + h];
        float a2 = g_alpha[(p + 2) * NH + h];
        float a3 = g_alpha[(p + 3) * NH + h];
        float2 v0 = featp[s0 * 96 + fvec];
        float2 v1 = featp[s1 * 96 + fvec];
        float2 v2 = featp[s2 * 96 + fvec];
        float2 v3 = featp[s3 * 96 + fvec];
        acc0.x = fmaf(a0, v0.x, acc0.x); acc0.y = fmaf(a0, v0.y, acc0.y);
        acc1.x = fmaf(a1, v1.x, acc1.x); acc1.y = fmaf(a1, v1.y, acc1.y);
        acc2.x = fmaf(a2, v2.x, acc2.x); acc2.y = fmaf(a2, v2.y, acc2.y);
        acc3.x = fmaf(a3, v3.x, acc3.x); acc3.y = fmaf(a3, v3.y, acc3.y);
    }
    for (; p < b1; p++) {
        int s = g_csrc[p];
        float a = g_alpha[p * NH + h];
        float2 v = featp[s * 96 + fvec];
        acc0.x = fmaf(a, v.x, acc0.x);
        acc0.y = fmaf(a, v.y, acc0.y);
    }
    float2 o;
    o.x = (acc0.x + acc1.x + acc2.x + acc3.x) * si;
    o.y = (acc0.y + acc1.y + acc2.y + acc3.y) * si;
    ((float2*)g_rst)[d * 96 + fvec] = o;
}

// thread per (dst, head) for Fo=2
__global__ void k_aggr2_csr() {
    int i = blockIdx.x * blockDim.x + threadIdx.x;
    if (i >= NN * NH) return;
    int d = i / NH, h = i - d * NH;
    int b0 = g_off[d], b1 = g_off[d + 1];
    float a0 = 0.f, a1 = 0.f;
    float si = (b0 < b1) ? g_sinv[i] : 0.f;
    for (int p = b0; p < b1; p++) {
        int s = g_csrc[p];
        float a = g_alpha[p * NH + h];
        a0 = fmaf(a, g_feat[s * 6 + h * 2 + 0], a0);
        a1 = fmaf(a, g_feat[s * 6 + h * 2 + 1], a1);
    }
    g_rst[d * 6 + h * 2 + 0] = a0 * si;
    g_rst[d * 6 + h * 2 + 1] = a1 * si;
}

// out[n,f] = sum_h (rst[n,h,f] + bias[h,f])
__global__ void k_final(const float* __restrict__ bias, float* __restrict__ out, int fo) {
    int i = blockIdx.x * blockDim.x + threadIdx.x;
    if (i >= NN * fo) return;
    int n = i / fo, f = i - n * fo;
    float acc = 0.f;
    #pragma unroll
    for (int h = 0; h < NH; h++)
        acc += g_rst[n * NH * fo + h * fo + f] + __ldg(bias + h * fo + f);
    out[i] = acc;
}

// ---------------- host side ----------------
static inline int cdiv(int a, int b) { return (a + b - 1) / b; }

static void run_layer(const float* x, const float* W, const float* al,
                      const float* ar, const float* bias,
                      int fin, int fo, float* out) {
    const int B = 256;
    int ftot = NH * fo;
    if ((fin & 3) == 0 && (ftot & 3) == 0)
        k_gemm_v4x4<<<cdiv(NN * (ftot >> 2), B), B>>>(x, W, fin, ftot);
    else if ((ftot & 3) == 0)
        k_gemm_v4<<<cdiv(NN * (ftot >> 2), B), B>>>(x, W, fin, ftot);
    else
        k_gemm<<<cdiv(NN * ftot, B), B>>>(x, W, fin, ftot);
    k_attn<<<cdiv(NN * NH, B), B>>>(al, ar, fo);
    k_alpha<<<cdiv(NN * NH, B), B>>>();
    if (fo == 64)
        k_aggr64_csr<<<cdiv(NN * NH * 32, B), B>>>();
    else
        k_aggr2_csr<<<cdiv(NN * NH, B), B>>>();
    k_final<<<cdiv(NN * fo, B), B>>>(bias, out, fo);
}

extern "C" void kernel_launch(void* const* d_in, const int* in_sizes, int n_in,
                              void* d_out, int out_size) {
    const float* feats = (const float*)d_in[0];
    const int*   src   = (const int*)d_in[1];
    const int*   dst   = (const int*)d_in[2];
    const float* W1  = (const float*)d_in[3];
    const float* al1 = (const float*)d_in[4];
    const float* ar1 = (const float*)d_in[5];
    const float* b1  = (const float*)d_in[6];
    const float* W2  = (const float*)d_in[7];
    const float* al2 = (const float*)d_in[8];
    const float* ar2 = (const float*)d_in[9];
    const float* b2  = (const float*)d_in[10];
    const float* W3  = (const float*)d_in[11];
    const float* al3 = (const float*)d_in[12];
    const float* ar3 = (const float*)d_in[13];
    const float* b3  = (const float*)d_in[14];

    const int B = 256;

    // Build CSR once (reused by all 3 layers)
    k_zero_deg<<<cdiv(SCAN_NB * SCAN_B, B), B>>>();
    k_count<<<cdiv(NE, B), B>>>(dst);
    k_scan1<<<SCAN_NB, SCAN_B>>>();
    k_scan2<<<1, 128>>>();
    k_scan3<<<cdiv(SCAN_NB * SCAN_B, B), B>>>();
    k_fill<<<cdiv(NE, B), B>>>(src, dst);

    float* hbuf = nullptr;
    cudaGetSymbolAddress((void**)&hbuf, g_h);

    run_layer(feats, W1, al1, ar1, b1, 9,  64, hbuf);
    run_layer(hbuf,  W2, al2, ar2, b2, 64, 64, hbuf);
    run_layer(hbuf,  W3, al3, ar3, b3, 64, 2,  (float*)d_out);
}